// round 9
// baseline (speedup 1.0000x reference)
#include <cuda_runtime.h>
#include <cuda_fp16.h>
#include <cstdint>

// out[m,n] = relu( sum_k x[m,k] * W[n,k] + b[n] )
// M=131072, N=256, K=256 fp32 in/out.
// fp16 mma.sync m16n8k16 + ldmatrix. BM=128 BN=128 BK=32 (SW64 64B rows),
// 256 thr, 2 CTAs/SM (decoupled barrier domains), double buffer, full unroll.

#define BM   128
#define BN   128
#define NDIM 256
#define KDIM 256
#define BKH  32                      // K halves per chunk
#define NCH  (KDIM / BKH)            // 8 chunks

#define ABUF (BM * 64)               // 8 KB per stage (64B rows)
#define BBUF (BN * 64)               // 8 KB per stage
#define SMEM_BYTES (2 * ABUF + 2 * BBUF)   // 32 KB

__device__ __half g_Wh[NDIM * KDIM];       // 128 KB fp16 W

__global__ void convW_kernel(const float* __restrict__ W) {
    int i = blockIdx.x * 1024 + threadIdx.x;   // 64 x 1024
    g_Wh[i] = __float2half_rn(W[i]);
}

__device__ __forceinline__ uint32_t pack_h2(float lo, float hi) {
    uint32_t d;
    asm("cvt.rn.f16x2.f32 %0, %1, %2;" : "=r"(d) : "f"(hi), "f"(lo));
    return d;
}
__device__ __forceinline__ void ldsm_x4(uint32_t* r, uint32_t addr) {
    asm volatile("ldmatrix.sync.aligned.m8n8.x4.shared.b16 {%0,%1,%2,%3}, [%4];"
                 : "=r"(r[0]), "=r"(r[1]), "=r"(r[2]), "=r"(r[3]) : "r"(addr));
}

__global__ void __launch_bounds__(256, 2)
gemm_f16_dual(const float* __restrict__ X, const float* __restrict__ bias,
              float* __restrict__ Out)
{
    extern __shared__ char smem[];
    const uint32_t sbase = (uint32_t)__cvta_generic_to_shared(smem);
    const uint32_t sA[2] = { sbase,          sbase + ABUF };
    const uint32_t sB[2] = { sbase + 2*ABUF, sbase + 2*ABUF + BBUF };

    const int tid  = threadIdx.x;
    const int lane = tid & 31;
    const int warp = tid >> 5;          // 0..7
    const int warpM = warp & 3;         // 4 x 32-row M slices
    const int warpN = warp >> 2;        // 2 x 64-col N slices
    const int ctaM = blockIdx.x * BM;
    const int ctaN = blockIdx.y * BN;

    const int j   = lane & 7;           // row within 8x8 matrix
    const int mat = lane >> 3;          // which of 4 matrices

    // SW64 swizzle: 64B rows, 16B unit u -> u ^ ((row>>1)&3)
    // A x4: row-group = mat&1 (+8 rows), k16-unit = mat>>1
    uint32_t aOff[2];
#pragma unroll
    for (int mt = 0; mt < 2; mt++) {
        const int arow = warpM * 32 + mt * 16 + (mat & 1) * 8 + j;
        aOff[mt] = (uint32_t)(arow * 64 + (((mat >> 1) ^ ((arow >> 1) & 3)) << 4));
    }
    // B x4 per n16-pair p: row-group = mat>>1, k16-unit = mat&1
    uint32_t bOff[4];
#pragma unroll
    for (int p = 0; p < 4; p++) {
        const int brow = warpN * 64 + p * 16 + (mat >> 1) * 8 + j;
        bOff[p] = (uint32_t)(brow * 64 + (((mat & 1) ^ ((brow >> 1) & 3)) << 4));
    }

    float acc[2][8][4];
#pragma unroll
    for (int i = 0; i < 2; i++)
#pragma unroll
        for (int jj = 0; jj < 8; jj++)
#pragma unroll
            for (int q = 0; q < 4; q++) acc[i][jj][q] = 0.0f;

    // ---- A prefetch: 128 rows x 8 f4 = 1024 / 256 thr = 4 f4 (16 regs) ----
    float4 pf[4];
    auto ldgA = [&](int ch) {
#pragma unroll
        for (int i = 0; i < 4; i++) {
            int f = tid + i * 256;
            int row = f >> 3, q = f & 7;
            pf[i] = __ldg((const float4*)(X + (size_t)(ctaM + row) * KDIM + ch * BKH + q * 4));
        }
    };
    auto stsA = [&](int buf) {
#pragma unroll
        for (int i = 0; i < 4; i++) {
            int f = tid + i * 256;
            int row = f >> 3, q = f & 7;           // q = 8B slot (fp16)
            uint32_t h01 = pack_h2(pf[i].x, pf[i].y);
            uint32_t h23 = pack_h2(pf[i].z, pf[i].w);
            uint32_t addr = sA[buf] + row * 64
                          + ((((q >> 1) ^ ((row >> 1) & 3)) << 4) | ((q & 1) << 3));
            asm volatile("st.shared.v2.b32 [%0], {%1, %2};"
                         :: "r"(addr), "r"(h01), "r"(h23) : "memory");
        }
    };
    auto cpB = [&](int ch, int buf) {
#pragma unroll
        for (int i = 0; i < 2; i++) {              // 128 rows x 4 x 16B = 512
            int s = tid + i * 256;
            int row = s >> 2, u = s & 3;
            uint32_t dst = sB[buf] + row * 64 + ((u ^ ((row >> 1) & 3)) << 4);
            const __half* src = g_Wh + (size_t)(ctaN + row) * KDIM + ch * BKH + u * 8;
            asm volatile("cp.async.cg.shared.global [%0], [%1], 16;"
                         :: "r"(dst), "l"(src));
        }
    };

    // ---- prologue ----
    ldgA(0);
    cpB(0, 0);
    asm volatile("cp.async.commit_group;" ::: "memory");

#pragma unroll
    for (int ch = 0; ch < NCH; ++ch) {
        const int buf = ch & 1;
        stsA(buf);                                 // chunk ch A (pf from prev iter)
        asm volatile("cp.async.wait_group 0;" ::: "memory");
        __syncthreads();
        if (ch + 1 < NCH) {
            ldgA(ch + 1);
            cpB(ch + 1, buf ^ 1);
            asm volatile("cp.async.commit_group;" ::: "memory");
        }

        const uint32_t aA0 = sA[buf] + aOff[0];
        const uint32_t aA1 = sA[buf] + aOff[1];
        const uint32_t bA0 = sB[buf] + bOff[0];
        const uint32_t bA1 = sB[buf] + bOff[1];
        const uint32_t bA2 = sB[buf] + bOff[2];
        const uint32_t bA3 = sB[buf] + bOff[3];

#pragma unroll
        for (int ks = 0; ks < 2; ks++) {
            const uint32_t x = (uint32_t)(ks << 5);    // k16-step XOR (16B-unit bit1)
            uint32_t a[2][4], b[4][4];
            ldsm_x4(a[0], aA0 ^ x);
            ldsm_x4(a[1], aA1 ^ x);
            ldsm_x4(b[0], bA0 ^ x);
            ldsm_x4(b[1], bA1 ^ x);
            ldsm_x4(b[2], bA2 ^ x);
            ldsm_x4(b[3], bA3 ^ x);
#pragma unroll
            for (int p = 0; p < 4; p++) {
#pragma unroll
                for (int s = 0; s < 2; s++) {
                    const int nt = 2 * p + s;
#pragma unroll
                    for (int mt = 0; mt < 2; mt++) {
                        asm volatile(
                            "mma.sync.aligned.m16n8k16.row.col.f32.f16.f16.f32 "
                            "{%0,%1,%2,%3}, {%4,%5,%6,%7}, {%8,%9}, {%0,%1,%2,%3};\n"
                            : "+f"(acc[mt][nt][0]), "+f"(acc[mt][nt][1]),
                              "+f"(acc[mt][nt][2]), "+f"(acc[mt][nt][3])
                            : "r"(a[mt][0]), "r"(a[mt][1]), "r"(a[mt][2]), "r"(a[mt][3]),
                              "r"(b[p][2*s]), "r"(b[p][2*s+1]));
                    }
                }
            }
        }
    }

    // ---- epilogue: bias + relu, float2 stores ----
    const int xr = lane >> 2;
#pragma unroll
    for (int mt = 0; mt < 2; mt++) {
        const int m0 = ctaM + warpM * 32 + mt * 16 + xr;
#pragma unroll
        for (int nt = 0; nt < 8; nt++) {
            const int n0 = ctaN + warpN * 64 + nt * 8 + 2 * (lane & 3);
            const float bv0 = __ldg(&bias[n0]);
            const float bv1 = __ldg(&bias[n0 + 1]);
            float v0 = fmaxf(acc[mt][nt][0] + bv0, 0.0f);
            float v1 = fmaxf(acc[mt][nt][1] + bv1, 0.0f);
            float v2 = fmaxf(acc[mt][nt][2] + bv0, 0.0f);
            float v3 = fmaxf(acc[mt][nt][3] + bv1, 0.0f);
            *(float2*)&Out[(size_t)m0 * NDIM + n0]       = make_float2(v0, v1);
            *(float2*)&Out[(size_t)(m0 + 8) * NDIM + n0] = make_float2(v2, v3);
        }
    }
}

extern "C" void kernel_launch(void* const* d_in, const int* in_sizes, int n_in,
                              void* d_out, int out_size)
{
    const float* x = (const float*)d_in[0];   // [131072, 256]
    const float* W = (const float*)d_in[1];   // [256, 256]
    const float* b = (const float*)d_in[2];   // [256]
    float* out = (float*)d_out;

    convW_kernel<<<64, 1024>>>(W);

    cudaFuncSetAttribute(gemm_f16_dual,
                         cudaFuncAttributeMaxDynamicSharedMemorySize, SMEM_BYTES);
    dim3 grid(131072 / BM, NDIM / BN);        // (1024, 2) = 2048 CTAs
    gemm_f16_dual<<<grid, 256, SMEM_BYTES>>>(x, b, out);
}